// round 13
// baseline (speedup 1.0000x reference)
#include <cuda_runtime.h>
#include <cstdint>

constexpr int Bsz  = 8;
constexpr int Cdim = 512;
constexpr int Ldim = 8192;
constexpr int Hn   = 8;
constexpr int Dh   = 64;

// ---------------- scratch (static device arrays; never passed as kernel args) --
__device__ float g_Gpart[4ull * Bsz * Cdim * Cdim];
__device__ float g_G[(size_t)Bsz * Cdim * Cdim];
__device__ float g_kvpart[8ull * Bsz * Hn * Dh * Dh];
__device__ float g_W2[(size_t)Bsz * Cdim * Cdim];
__device__ float g_W3[(size_t)Bsz * Cdim * Cdim];

// packed dual-FMA helpers (base PTX, sm_100+)
static __device__ __forceinline__ unsigned long long dup2(float a) {
    unsigned long long r;
    asm("mov.b64 %0, {%1, %1};" : "=l"(r) : "f"(a));
    return r;
}
static __device__ __forceinline__ void fma2(unsigned long long& c,
                                            unsigned long long a,
                                            unsigned long long b) {
    asm("fma.rn.f32x2 %0, %1, %2, %0;" : "+l"(c) : "l"(a), "l"(b));
}
static __device__ __forceinline__ float lo32(unsigned long long v) {
    return __uint_as_float((unsigned)(v & 0xFFFFFFFFull));
}
static __device__ __forceinline__ float hi32(unsigned long long v) {
    return __uint_as_float((unsigned)(v >> 32));
}

// ---------------------------------------------------------------------------
// Kernel 1: Gram partials; f32x2 with PRE-DUPLICATED B in smem (no movs in
// the kk loop).  G[b] = Xg[b] @ Xg[b]^T, 10 symmetric tile pairs, split-K=4.
// acc layout: 4 m-pairs x 8 n columns (pair = adjacent m rows).
// ---------------------------------------------------------------------------
__global__ __launch_bounds__(256, 2) void gram_kernel(const float* __restrict__ Xg) {
    const int pair = blockIdx.x, ks = blockIdx.y, b = blockIdx.z;
    int ti = 0, t = pair;
    while (t >= 4 - ti) { t -= 4 - ti; ti++; }
    const int tj = ti + t;

    const float* X   = Xg + (size_t)b * Cdim * Ldim;
    const float* Ag0 = X + (size_t)ti * 128 * Ldim;
    const float* Bg0 = X + (size_t)tj * 128 * Ldim;
    const int k0 = ks * 2048;

    __shared__ float As[16][132];   // [k][m]
    __shared__ float Bd[16][264];   // [k][2n] duplicated pairs

    const int tid = threadIdx.x;
    const int tx = tid & 15, ty = tid >> 4;
    const int lrow = tid >> 2, lc4 = tid & 3;

    unsigned long long acc[4][8];
#pragma unroll
    for (int i = 0; i < 4; i++)
#pragma unroll
        for (int j = 0; j < 8; j++) acc[i][j] = 0ull;

    const float* ApA = Ag0 + (size_t)lrow * Ldim + lc4 * 4 + k0;
    const float* ApB = Ag0 + (size_t)(lrow + 64) * Ldim + lc4 * 4 + k0;
    const float* BpA = Bg0 + (size_t)lrow * Ldim + lc4 * 4 + k0;
    const float* BpB = Bg0 + (size_t)(lrow + 64) * Ldim + lc4 * 4 + k0;

    float4 a0 = *(const float4*)(ApA);
    float4 a1 = *(const float4*)(ApB);
    float4 b0 = *(const float4*)(BpA);
    float4 b1 = *(const float4*)(BpB);

    for (int kt = 0; kt < 2048; kt += 16) {
        __syncthreads();
        As[lc4*4+0][lrow]    = a0.x; As[lc4*4+1][lrow]    = a0.y;
        As[lc4*4+2][lrow]    = a0.z; As[lc4*4+3][lrow]    = a0.w;
        As[lc4*4+0][lrow+64] = a1.x; As[lc4*4+1][lrow+64] = a1.y;
        As[lc4*4+2][lrow+64] = a1.z; As[lc4*4+3][lrow+64] = a1.w;
        // B duplicated: value for (k=lc4*4+q, n=lrow[,+64]) -> cols 2n,2n+1
        *(unsigned long long*)&Bd[lc4*4+0][2*lrow] = dup2(b0.x);
        *(unsigned long long*)&Bd[lc4*4+1][2*lrow] = dup2(b0.y);
        *(unsigned long long*)&Bd[lc4*4+2][2*lrow] = dup2(b0.z);
        *(unsigned long long*)&Bd[lc4*4+3][2*lrow] = dup2(b0.w);
        *(unsigned long long*)&Bd[lc4*4+0][128+2*lrow] = dup2(b1.x);
        *(unsigned long long*)&Bd[lc4*4+1][128+2*lrow] = dup2(b1.y);
        *(unsigned long long*)&Bd[lc4*4+2][128+2*lrow] = dup2(b1.z);
        *(unsigned long long*)&Bd[lc4*4+3][128+2*lrow] = dup2(b1.w);
        __syncthreads();
        if (kt + 16 < 2048) {   // prefetch next stage under the compute
            a0 = *(const float4*)(ApA + kt + 16);
            a1 = *(const float4*)(ApB + kt + 16);
            b0 = *(const float4*)(BpA + kt + 16);
            b1 = *(const float4*)(BpB + kt + 16);
        }
#pragma unroll
        for (int kk = 0; kk < 16; kk++) {
            float4 aq0 = *(const float4*)&As[kk][ty*4];
            float4 aq1 = *(const float4*)&As[kk][64 + ty*4];
            unsigned long long ap[4];
            ap[0] = *(unsigned long long*)&aq0.x;
            ap[1] = *(unsigned long long*)&aq0.z;
            ap[2] = *(unsigned long long*)&aq1.x;
            ap[3] = *(unsigned long long*)&aq1.z;
            float4 bq0 = *(const float4*)&Bd[kk][tx*8];
            float4 bq1 = *(const float4*)&Bd[kk][tx*8 + 4];
            float4 bq2 = *(const float4*)&Bd[kk][128 + tx*8];
            float4 bq3 = *(const float4*)&Bd[kk][128 + tx*8 + 4];
            unsigned long long bp[8];
            bp[0] = *(unsigned long long*)&bq0.x; bp[1] = *(unsigned long long*)&bq0.z;
            bp[2] = *(unsigned long long*)&bq1.x; bp[3] = *(unsigned long long*)&bq1.z;
            bp[4] = *(unsigned long long*)&bq2.x; bp[5] = *(unsigned long long*)&bq2.z;
            bp[6] = *(unsigned long long*)&bq3.x; bp[7] = *(unsigned long long*)&bq3.z;
#pragma unroll
            for (int i = 0; i < 4; i++)
#pragma unroll
                for (int j = 0; j < 8; j++) fma2(acc[i][j], ap[i], bp[j]);
        }
    }

    float* Gp = g_Gpart + ((size_t)ks * Bsz + b) * Cdim * Cdim;
#pragma unroll
    for (int ip = 0; ip < 4; ip++) {
        const int me = ti * 128 + ((ip < 2) ? (ty*4 + 2*ip) : (64 + ty*4 + 2*(ip - 2)));
        const int mo = me + 1;
        const int n0 = tj * 128 + tx*4;
        float4 ve0 = make_float4(lo32(acc[ip][0]), lo32(acc[ip][1]),
                                 lo32(acc[ip][2]), lo32(acc[ip][3]));
        float4 ve1 = make_float4(lo32(acc[ip][4]), lo32(acc[ip][5]),
                                 lo32(acc[ip][6]), lo32(acc[ip][7]));
        float4 vo0 = make_float4(hi32(acc[ip][0]), hi32(acc[ip][1]),
                                 hi32(acc[ip][2]), hi32(acc[ip][3]));
        float4 vo1 = make_float4(hi32(acc[ip][4]), hi32(acc[ip][5]),
                                 hi32(acc[ip][6]), hi32(acc[ip][7]));
        *(float4*)(Gp + (size_t)me * Cdim + n0)      = ve0;
        *(float4*)(Gp + (size_t)me * Cdim + n0 + 64) = ve1;
        *(float4*)(Gp + (size_t)mo * Cdim + n0)      = vo0;
        *(float4*)(Gp + (size_t)mo * Cdim + n0 + 64) = vo1;
        if (ti != tj) {
#pragma unroll
            for (int j = 0; j < 8; j++) {
                const int n = tj * 128 + ((j < 4) ? (tx*4 + j) : (64 + tx*4 + j - 4));
                Gp[(size_t)n * Cdim + me] = lo32(acc[ip][j]);
                Gp[(size_t)n * Cdim + mo] = hi32(acc[ip][j]);
            }
        }
    }
}

// Kernel 2: reduce the 4 split-K slabs (deterministic).
__global__ void greduce_kernel() {
    const size_t n   = (size_t)Bsz * Cdim * Cdim;
    const size_t idx = (size_t)blockIdx.x * blockDim.x + threadIdx.x;
    if (idx < n) {
        g_G[idx] = g_Gpart[idx] + g_Gpart[n + idx] + g_Gpart[2*n + idx] + g_Gpart[3*n + idx];
    }
}

// ---------------------------------------------------------------------------
// Kernel 3: kv partials; phase-1 in f32x2 (m-pair packing, dup-b via mov).
// kv[b,h] = Wk_h @ G[b] @ Wv_h^T
// ---------------------------------------------------------------------------
__global__ __launch_bounds__(256) void kv_kernel(const float* __restrict__ Wk,
                                                 const float* __restrict__ Wv) {
    const int ct = blockIdx.x;
    const int h  = blockIdx.y;
    const int b  = blockIdx.z;
    const float* G = g_G + (size_t)b * Cdim * Cdim;
    const int c0 = ct * 64;

    __shared__ float Wks[16][68];
    __shared__ float Gs[16][68];
    __shared__ float Ts[64][68];
    __shared__ float Wvs[64][68];

    const int tid = threadIdx.x;
    const int tx = tid & 15, ty = tid >> 4;

    unsigned long long accp[2][4];
#pragma unroll
    for (int p = 0; p < 2; p++)
#pragma unroll
        for (int j = 0; j < 4; j++) accp[p][j] = 0ull;

    for (int k = 0; k < 512; k += 16) {
        const int row = tid >> 2, c4 = tid & 3;
        float4 w4 = *(const float4*)(Wk + (size_t)(h*64 + row) * Cdim + k + c4*4);
        const int kr = tid >> 4, f4 = tid & 15;
        float4 g4 = *(const float4*)(G + (size_t)(k + kr) * Cdim + c0 + f4*4);
        __syncthreads();
        Wks[c4*4+0][row] = w4.x; Wks[c4*4+1][row] = w4.y;
        Wks[c4*4+2][row] = w4.z; Wks[c4*4+3][row] = w4.w;
        *(float4*)&Gs[kr][f4*4] = g4;
        __syncthreads();
#pragma unroll
        for (int kk = 0; kk < 16; kk++) {
            float4 aq = *(const float4*)&Wks[kk][ty*4];
            unsigned long long ap0 = *(unsigned long long*)&aq.x;
            unsigned long long ap1 = *(unsigned long long*)&aq.z;
            float4 gq = *(const float4*)&Gs[kk][tx*4];
            unsigned long long bd[4] = { dup2(gq.x), dup2(gq.y), dup2(gq.z), dup2(gq.w) };
#pragma unroll
            for (int j = 0; j < 4; j++) { fma2(accp[0][j], ap0, bd[j]); fma2(accp[1][j], ap1, bd[j]); }
        }
    }
#pragma unroll
    for (int p = 0; p < 2; p++)
#pragma unroll
        for (int j = 0; j < 4; j++) {
            Ts[ty*4 + 2*p][tx*4 + j]     = lo32(accp[p][j]);
            Ts[ty*4 + 2*p + 1][tx*4 + j] = hi32(accp[p][j]);
        }

#pragma unroll
    for (int q = 0; q < 4; q++) {
        const int idx = tid + q*256;
        const int er = idx >> 4, f4 = idx & 15;
        *(float4*)&Wvs[er][f4*4] = *(const float4*)(Wv + (size_t)(h*64 + er) * Cdim + c0 + f4*4);
    }
    __syncthreads();

    float acc2[4][4];
#pragma unroll
    for (int i = 0; i < 4; i++)
#pragma unroll
        for (int j = 0; j < 4; j++) acc2[i][j] = 0.f;
    for (int j = 0; j < 64; j++) {
        float a4[4], b4[4];
#pragma unroll
        for (int i = 0; i < 4; i++) a4[i] = Ts[ty*4+i][j];
#pragma unroll
        for (int e = 0; e < 4; e++) b4[e] = Wvs[tx*4+e][j];
#pragma unroll
        for (int i = 0; i < 4; i++)
#pragma unroll
            for (int e = 0; e < 4; e++) acc2[i][e] += a4[i] * b4[e];
    }
    float* kvp = g_kvpart + (((size_t)ct * Bsz + b) * Hn + h) * (Dh * Dh);
#pragma unroll
    for (int i = 0; i < 4; i++)
#pragma unroll
        for (int e = 0; e < 4; e++)
            kvp[(size_t)(ty*4 + i) * 64 + tx*4 + e] = acc2[i][e];
}

// ---------------------------------------------------------------------------
// Kernel 4: W2 (fp32, proven)
// ---------------------------------------------------------------------------
__global__ __launch_bounds__(256) void w2_kernel(const float* __restrict__ Wo) {
    const int ot = blockIdx.x;
    const int h  = blockIdx.y;
    const int b  = blockIdx.z;

    __shared__ float Wos[64][68];
    __shared__ float kvs[64][68];

    const int tid = threadIdx.x;
    const int tx = tid & 15, ty = tid >> 4;

#pragma unroll
    for (int q = 0; q < 4; q++) {
        const int idx = tid + q*256;
        const int r = idx >> 4, f4 = idx & 15;
        *(float4*)&Wos[r][f4*4] = *(const float4*)(Wo + (size_t)(ot*64 + r) * Cdim + h*64 + f4*4);
    }
#pragma unroll
    for (int q = 0; q < 4; q++) {
        const int idx = tid + q*256;
        const int d = idx >> 4, f4 = idx & 15;
        float4 s = make_float4(0.f, 0.f, 0.f, 0.f);
        for (int t = 0; t < 8; t++) {
            const float4 v = *(const float4*)(g_kvpart +
                (((size_t)t * Bsz + b) * Hn + h) * 4096 + (size_t)d * 64 + f4*4);
            s.x += v.x; s.y += v.y; s.z += v.z; s.w += v.w;
        }
        *(float4*)&kvs[d][f4*4] = s;
    }
    __syncthreads();

    float acc[4][4];
#pragma unroll
    for (int i = 0; i < 4; i++)
#pragma unroll
        for (int j = 0; j < 4; j++) acc[i][j] = 0.f;
    for (int e = 0; e < 64; e++) {
        float a4[4], b4[4];
#pragma unroll
        for (int i = 0; i < 4; i++) a4[i] = Wos[ty*4+i][e];
#pragma unroll
        for (int j = 0; j < 4; j++) b4[j] = kvs[tx*4+j][e];
#pragma unroll
        for (int i = 0; i < 4; i++)
#pragma unroll
            for (int j = 0; j < 4; j++) acc[i][j] += a4[i] * b4[j];
    }
    float* W2 = g_W2 + (size_t)b * Cdim * Cdim;
    const float inv = 1.f / 64.f;
#pragma unroll
    for (int i = 0; i < 4; i++)
#pragma unroll
        for (int j = 0; j < 4; j++)
            W2[(size_t)(ot*64 + ty*4 + i) * Cdim + h*64 + tx*4 + j] = acc[i][j] * inv;
}

// ---------------------------------------------------------------------------
// Kernel 5: W3 in f32x2 (m-pair packing): W3[b] = W2[b] @ Wq
// ---------------------------------------------------------------------------
__global__ __launch_bounds__(256) void w3_kernel(const float* __restrict__ Wq) {
    const int nt = blockIdx.x;
    const int mt = blockIdx.y;
    const int b  = blockIdx.z;
    const float* A = g_W2 + (size_t)b * Cdim * Cdim;

    __shared__ float As_[16][68];
    __shared__ float Bs_[16][68];

    const int tid = threadIdx.x;
    const int tx = tid & 15, ty = tid >> 4;

    unsigned long long accp[2][4];
#pragma unroll
    for (int p = 0; p < 2; p++)
#pragma unroll
        for (int j = 0; j < 4; j++) accp[p][j] = 0ull;

    for (int k = 0; k < 512; k += 16) {
        const int row = tid >> 2, c4 = tid & 3;
        float4 a4 = *(const float4*)(A + (size_t)(mt*64 + row) * Cdim + k + c4*4);
        const int kr = tid >> 4, f4 = tid & 15;
        float4 b4 = *(const float4*)(Wq + (size_t)(k + kr) * Cdim + nt*64 + f4*4);
        __syncthreads();
        As_[c4*4+0][row] = a4.x; As_[c4*4+1][row] = a4.y;
        As_[c4*4+2][row] = a4.z; As_[c4*4+3][row] = a4.w;
        *(float4*)&Bs_[kr][f4*4] = b4;
        __syncthreads();
#pragma unroll
        for (int kk = 0; kk < 16; kk++) {
            float4 aq = *(const float4*)&As_[kk][ty*4];
            unsigned long long ap0 = *(unsigned long long*)&aq.x;
            unsigned long long ap1 = *(unsigned long long*)&aq.z;
            float4 bq = *(const float4*)&Bs_[kk][tx*4];
            unsigned long long bd[4] = { dup2(bq.x), dup2(bq.y), dup2(bq.z), dup2(bq.w) };
#pragma unroll
            for (int j = 0; j < 4; j++) { fma2(accp[0][j], ap0, bd[j]); fma2(accp[1][j], ap1, bd[j]); }
        }
    }
    float* W3 = g_W3 + (size_t)b * Cdim * Cdim;
#pragma unroll
    for (int p = 0; p < 2; p++)
#pragma unroll
        for (int j = 0; j < 4; j++) {
            W3[(size_t)(mt*64 + ty*4 + 2*p) * Cdim + nt*64 + tx*4 + j]     = lo32(accp[p][j]);
            W3[(size_t)(mt*64 + ty*4 + 2*p + 1) * Cdim + nt*64 + tx*4 + j] = hi32(accp[p][j]);
        }
}

// ---------------------------------------------------------------------------
// Kernel 6: out; f32x2 with PRE-DUPLICATED B in smem.
// out[b] = W3[b] @ Xl[b]  (M=512, N=8192, K=512)
// ---------------------------------------------------------------------------
__global__ __launch_bounds__(256, 2) void out_kernel(const float* __restrict__ Xl,
                                                     float* __restrict__ Out) {
    const int nt = blockIdx.x;
    const int mt = blockIdx.y;
    const int b  = blockIdx.z;
    const float* A  = g_W3 + (size_t)b * Cdim * Cdim;
    const float* Bm = Xl + (size_t)b * Cdim * Ldim;
    float* O        = Out + (size_t)b * Cdim * Ldim;

    __shared__ float As[16][132];   // [k][m]
    __shared__ float Bd[16][264];   // [k][2n] duplicated

    const int tid = threadIdx.x;
    const int tx = tid & 15, ty = tid >> 4;
    const int arow = tid >> 2, ac4 = tid & 3;
    const int kr0 = tid >> 5, c40 = tid & 31;
    const int n0 = nt * 128;

    unsigned long long acc[4][8];
#pragma unroll
    for (int i = 0; i < 4; i++)
#pragma unroll
        for (int j = 0; j < 8; j++) acc[i][j] = 0ull;

    const float* ApA = A + (size_t)(mt*128 + arow) * Cdim + ac4 * 4;
    const float* ApB = A + (size_t)(mt*128 + arow + 64) * Cdim + ac4 * 4;
    const float* BpA = Bm + (size_t)kr0 * Ldim + n0 + c40 * 4;
    const float* BpB = Bm + (size_t)(kr0 + 8) * Ldim + n0 + c40 * 4;

    float4 a0 = *(const float4*)(ApA);
    float4 a1 = *(const float4*)(ApB);
    float4 b0 = *(const float4*)(BpA);
    float4 b1 = *(const float4*)(BpB);

    for (int k = 0; k < 512; k += 16) {
        __syncthreads();
        As[ac4*4+0][arow]    = a0.x; As[ac4*4+1][arow]    = a0.y;
        As[ac4*4+2][arow]    = a0.z; As[ac4*4+3][arow]    = a0.w;
        As[ac4*4+0][arow+64] = a1.x; As[ac4*4+1][arow+64] = a1.y;
        As[ac4*4+2][arow+64] = a1.z; As[ac4*4+3][arow+64] = a1.w;
        // b0 = (k=kr0, n=c40*4..+3): duplicated pairs are contiguous -> 2 STS.128
        {
            float4 d0 = make_float4(b0.x, b0.x, b0.y, b0.y);
            float4 d1 = make_float4(b0.z, b0.z, b0.w, b0.w);
            *(float4*)&Bd[kr0][c40*8]     = d0;
            *(float4*)&Bd[kr0][c40*8 + 4] = d1;
            float4 d2 = make_float4(b1.x, b1.x, b1.y, b1.y);
            float4 d3 = make_float4(b1.z, b1.z, b1.w, b1.w);
            *(float4*)&Bd[kr0 + 8][c40*8]     = d2;
            *(float4*)&Bd[kr0 + 8][c40*8 + 4] = d3;
        }
        __syncthreads();
        if (k + 16 < 512) {
            a0 = *(const float4*)(ApA + k + 16);
            a1 = *(const float4*)(ApB + k + 16);
            b0 = *(const float4*)(BpA + (size_t)(k + 16) * Ldim);
            b1 = *(const float4*)(BpB + (size_t)(k + 16) * Ldim);
        }
#pragma unroll
        for (int kk = 0; kk < 16; kk++) {
            float4 aq0 = *(const float4*)&As[kk][ty*4];
            float4 aq1 = *(const float4*)&As[kk][64 + ty*4];
            unsigned long long ap[4];
            ap[0] = *(unsigned long long*)&aq0.x;
            ap[1] = *(unsigned long long*)&aq0.z;
            ap[2] = *(unsigned long long*)&aq1.x;
            ap[3] = *(unsigned long long*)&aq1.z;
            float4 bq0 = *(const float4*)&Bd[kk][tx*8];
            float4 bq1 = *(const float4*)&Bd[kk][tx*8 + 4];
            float4 bq2 = *(const float4*)&Bd[kk][128 + tx*8];
            float4 bq3 = *(const float4*)&Bd[kk][128 + tx*8 + 4];
            unsigned long long bp[8];
            bp[0] = *(unsigned long long*)&bq0.x; bp[1] = *(unsigned long long*)&bq0.z;
            bp[2] = *(unsigned long long*)&bq1.x; bp[3] = *(unsigned long long*)&bq1.z;
            bp[4] = *(unsigned long long*)&bq2.x; bp[5] = *(unsigned long long*)&bq2.z;
            bp[6] = *(unsigned long long*)&bq3.x; bp[7] = *(unsigned long long*)&bq3.z;
#pragma unroll
            for (int i = 0; i < 4; i++)
#pragma unroll
                for (int j = 0; j < 8; j++) fma2(acc[i][j], ap[i], bp[j]);
        }
    }

#pragma unroll
    for (int ip = 0; ip < 4; ip++) {
        const int me = mt*128 + ((ip < 2) ? (ty*4 + 2*ip) : (64 + ty*4 + 2*(ip - 2)));
        const int mo = me + 1;
        float4 ve0 = make_float4(lo32(acc[ip][0]), lo32(acc[ip][1]),
                                 lo32(acc[ip][2]), lo32(acc[ip][3]));
        float4 ve1 = make_float4(lo32(acc[ip][4]), lo32(acc[ip][5]),
                                 lo32(acc[ip][6]), lo32(acc[ip][7]));
        float4 vo0 = make_float4(hi32(acc[ip][0]), hi32(acc[ip][1]),
                                 hi32(acc[ip][2]), hi32(acc[ip][3]));
        float4 vo1 = make_float4(hi32(acc[ip][4]), hi32(acc[ip][5]),
                                 hi32(acc[ip][6]), hi32(acc[ip][7]));
        *(float4*)(O + (size_t)me * Ldim + n0 + tx*4)      = ve0;
        *(float4*)(O + (size_t)me * Ldim + n0 + 64 + tx*4) = ve1;
        *(float4*)(O + (size_t)mo * Ldim + n0 + tx*4)      = vo0;
        *(float4*)(O + (size_t)mo * Ldim + n0 + 64 + tx*4) = vo1;
    }
}

// ---------------------------------------------------------------------------
extern "C" void kernel_launch(void* const* d_in, const int* in_sizes, int n_in,
                              void* d_out, int out_size) {
    const float* x_local  = (const float*)d_in[0];
    const float* x_global = (const float*)d_in[1];
    const float* Wq       = (const float*)d_in[2];
    const float* Wk       = (const float*)d_in[3];
    const float* Wv       = (const float*)d_in[4];
    const float* Wo       = (const float*)d_in[5];
    float* out = (float*)d_out;

    gram_kernel<<<dim3(10, 4, 8), 256>>>(x_global);
    greduce_kernel<<<dim3(8192), 256>>>();
    kv_kernel<<<dim3(8, 8, 8), 256>>>(Wk, Wv);
    w2_kernel<<<dim3(8, 8, 8), 256>>>(Wo);
    w3_kernel<<<dim3(8, 8, 8), 256>>>(Wq);
    out_kernel<<<dim3(64, 4, 8), 256>>>(x_local, out);
}

// round 14
// speedup vs baseline: 1.8407x; 1.8407x over previous
#include <cuda_runtime.h>
#include <cstdint>

constexpr int Bsz  = 8;
constexpr int Cdim = 512;
constexpr int Ldim = 8192;
constexpr int Hn   = 8;
constexpr int Dh   = 64;

// ---------------- scratch (static device arrays; never passed as kernel args) --
__device__ float g_Gpart[4ull * Bsz * Cdim * Cdim];
__device__ float g_G[(size_t)Bsz * Cdim * Cdim];
__device__ float g_kvpart[8ull * Bsz * Hn * Dh * Dh];
__device__ float g_W2[(size_t)Bsz * Cdim * Cdim];
__device__ float g_W3[(size_t)Bsz * Cdim * Cdim];

// packed dual-FMA helpers (base PTX, sm_100+)
static __device__ __forceinline__ unsigned long long dup2(float a) {
    unsigned long long r;
    asm("mov.b64 %0, {%1, %1};" : "=l"(r) : "f"(a));
    return r;
}
static __device__ __forceinline__ void fma2(unsigned long long& c,
                                            unsigned long long a,
                                            unsigned long long b) {
    asm("fma.rn.f32x2 %0, %1, %2, %0;" : "+l"(c) : "l"(a), "l"(b));
}
static __device__ __forceinline__ float lo32(unsigned long long v) {
    return __uint_as_float((unsigned)(v & 0xFFFFFFFFull));
}
static __device__ __forceinline__ float hi32(unsigned long long v) {
    return __uint_as_float((unsigned)(v >> 32));
}

// ---------------------------------------------------------------------------
// Kernel 1: Gram partials; f32x2, 8m x 16n microtile (128 threads/block).
// G[b] = Xg[b] @ Xg[b]^T, 10 symmetric 128x128 tile pairs, split-K=4 slabs.
// acc[i][j]: i = m row (ty*8+i), j = n-pair (n = 32*(j>>1) + tx*4 + 2*(j&1)).
// ---------------------------------------------------------------------------
__global__ __launch_bounds__(128, 2) void gram_kernel(const float* __restrict__ Xg) {
    const int pair = blockIdx.x, ks = blockIdx.y, b = blockIdx.z;
    int ti = 0, t = pair;
    while (t >= 4 - ti) { t -= 4 - ti; ti++; }
    const int tj = ti + t;

    const float* X   = Xg + (size_t)b * Cdim * Ldim;
    const float* Ag0 = X + (size_t)ti * 128 * Ldim;
    const float* Bg0 = X + (size_t)tj * 128 * Ldim;
    const int k0 = ks * 2048;

    __shared__ float As[16][132];   // [k][m]
    __shared__ float Bs[16][132];   // [k][n]

    const int tid = threadIdx.x;
    const int tx = tid & 7, ty = tid >> 3;

    // loader lanes: 4 chunks each for A and B (128 rows x 4 float4-chunks)
    int lrow[4], lc4[4];
#pragma unroll
    for (int q = 0; q < 4; q++) {
        const int id = tid + q * 128;
        lrow[q] = id >> 2; lc4[q] = id & 3;
    }
    const float* pA[4];
    const float* pB[4];
#pragma unroll
    for (int q = 0; q < 4; q++) {
        pA[q] = Ag0 + (size_t)lrow[q] * Ldim + lc4[q] * 4 + k0;
        pB[q] = Bg0 + (size_t)lrow[q] * Ldim + lc4[q] * 4 + k0;
    }

    unsigned long long acc[8][8];
#pragma unroll
    for (int i = 0; i < 8; i++)
#pragma unroll
        for (int j = 0; j < 8; j++) acc[i][j] = 0ull;

    float4 fa[4], fb[4];
#pragma unroll
    for (int q = 0; q < 4; q++) { fa[q] = *(const float4*)(pA[q]); fb[q] = *(const float4*)(pB[q]); }

    for (int kt = 0; kt < 2048; kt += 16) {
        __syncthreads();
#pragma unroll
        for (int q = 0; q < 4; q++) {
            As[lc4[q]*4+0][lrow[q]] = fa[q].x; As[lc4[q]*4+1][lrow[q]] = fa[q].y;
            As[lc4[q]*4+2][lrow[q]] = fa[q].z; As[lc4[q]*4+3][lrow[q]] = fa[q].w;
            Bs[lc4[q]*4+0][lrow[q]] = fb[q].x; Bs[lc4[q]*4+1][lrow[q]] = fb[q].y;
            Bs[lc4[q]*4+2][lrow[q]] = fb[q].z; Bs[lc4[q]*4+3][lrow[q]] = fb[q].w;
        }
        __syncthreads();
        if (kt + 16 < 2048) {
#pragma unroll
            for (int q = 0; q < 4; q++) {
                fa[q] = *(const float4*)(pA[q] + kt + 16);
                fb[q] = *(const float4*)(pB[q] + kt + 16);
            }
        }
#pragma unroll
        for (int kk = 0; kk < 16; kk++) {
            float af[8];
            *(float4*)&af[0] = *(const float4*)&As[kk][ty*8];
            *(float4*)&af[4] = *(const float4*)&As[kk][ty*8 + 4];
            float4 bq0 = *(const float4*)&Bs[kk][tx*4];
            float4 bq1 = *(const float4*)&Bs[kk][32 + tx*4];
            float4 bq2 = *(const float4*)&Bs[kk][64 + tx*4];
            float4 bq3 = *(const float4*)&Bs[kk][96 + tx*4];
            unsigned long long bp[8];
            bp[0] = *(unsigned long long*)&bq0.x; bp[1] = *(unsigned long long*)&bq0.z;
            bp[2] = *(unsigned long long*)&bq1.x; bp[3] = *(unsigned long long*)&bq1.z;
            bp[4] = *(unsigned long long*)&bq2.x; bp[5] = *(unsigned long long*)&bq2.z;
            bp[6] = *(unsigned long long*)&bq3.x; bp[7] = *(unsigned long long*)&bq3.z;
#pragma unroll
            for (int i = 0; i < 8; i++) {
                const unsigned long long aa = dup2(af[i]);
#pragma unroll
                for (int j = 0; j < 8; j++) fma2(acc[i][j], aa, bp[j]);
            }
        }
    }

    float* Gp = g_Gpart + ((size_t)ks * Bsz + b) * Cdim * Cdim;
#pragma unroll
    for (int i = 0; i < 8; i++) {
        const int m = ti * 128 + ty * 8 + i;
#pragma unroll
        for (int c = 0; c < 4; c++) {
            const int n = tj * 128 + 32 * c + tx * 4;
            float4 v = make_float4(lo32(acc[i][2*c]), hi32(acc[i][2*c]),
                                   lo32(acc[i][2*c+1]), hi32(acc[i][2*c+1]));
            *(float4*)(Gp + (size_t)m * Cdim + n) = v;
            if (ti != tj) {
                Gp[(size_t)n * Cdim + m]       = v.x;
                Gp[(size_t)(n + 1) * Cdim + m] = v.y;
                Gp[(size_t)(n + 2) * Cdim + m] = v.z;
                Gp[(size_t)(n + 3) * Cdim + m] = v.w;
            }
        }
    }
}

// Kernel 2: reduce the 4 split-K slabs (deterministic).
__global__ void greduce_kernel() {
    const size_t n   = (size_t)Bsz * Cdim * Cdim;
    const size_t idx = (size_t)blockIdx.x * blockDim.x + threadIdx.x;
    if (idx < n) {
        g_G[idx] = g_Gpart[idx] + g_Gpart[n + idx] + g_Gpart[2*n + idx] + g_Gpart[3*n + idx];
    }
}

// ---------------------------------------------------------------------------
// Kernel 3: kv partials (fp32, proven): kv[b,h] = Wk_h @ G[b] @ Wv_h^T
// ---------------------------------------------------------------------------
__global__ __launch_bounds__(256) void kv_kernel(const float* __restrict__ Wk,
                                                 const float* __restrict__ Wv) {
    const int ct = blockIdx.x;
    const int h  = blockIdx.y;
    const int b  = blockIdx.z;
    const float* G = g_G + (size_t)b * Cdim * Cdim;
    const int c0 = ct * 64;

    __shared__ float Wks[16][68];
    __shared__ float Gs[16][68];
    __shared__ float Ts[64][68];
    __shared__ float Wvs[64][68];

    const int tid = threadIdx.x;
    const int tx = tid & 15, ty = tid >> 4;

    float acc[4][4];
#pragma unroll
    for (int i = 0; i < 4; i++)
#pragma unroll
        for (int j = 0; j < 4; j++) acc[i][j] = 0.f;

    for (int k = 0; k < 512; k += 16) {
        const int row = tid >> 2, c4 = tid & 3;
        float4 w4 = *(const float4*)(Wk + (size_t)(h*64 + row) * Cdim + k + c4*4);
        const int kr = tid >> 4, f4 = tid & 15;
        float4 g4 = *(const float4*)(G + (size_t)(k + kr) * Cdim + c0 + f4*4);
        __syncthreads();
        Wks[c4*4+0][row] = w4.x; Wks[c4*4+1][row] = w4.y;
        Wks[c4*4+2][row] = w4.z; Wks[c4*4+3][row] = w4.w;
        *(float4*)&Gs[kr][f4*4] = g4;
        __syncthreads();
#pragma unroll
        for (int kk = 0; kk < 16; kk++) {
            float a4[4], b4[4];
            *(float4*)&a4[0] = *(const float4*)&Wks[kk][ty*4];
            *(float4*)&b4[0] = *(const float4*)&Gs[kk][tx*4];
#pragma unroll
            for (int i = 0; i < 4; i++)
#pragma unroll
                for (int j = 0; j < 4; j++) acc[i][j] += a4[i] * b4[j];
        }
    }
#pragma unroll
    for (int i = 0; i < 4; i++)
#pragma unroll
        for (int j = 0; j < 4; j++) Ts[ty*4+i][tx*4+j] = acc[i][j];

#pragma unroll
    for (int q = 0; q < 4; q++) {
        const int idx = tid + q*256;
        const int er = idx >> 4, f4 = idx & 15;
        *(float4*)&Wvs[er][f4*4] = *(const float4*)(Wv + (size_t)(h*64 + er) * Cdim + c0 + f4*4);
    }
    __syncthreads();

    float acc2[4][4];
#pragma unroll
    for (int i = 0; i < 4; i++)
#pragma unroll
        for (int j = 0; j < 4; j++) acc2[i][j] = 0.f;
    for (int j = 0; j < 64; j++) {
        float a4[4], b4[4];
#pragma unroll
        for (int i = 0; i < 4; i++) a4[i] = Ts[ty*4+i][j];
#pragma unroll
        for (int e = 0; e < 4; e++) b4[e] = Wvs[tx*4+e][j];
#pragma unroll
        for (int i = 0; i < 4; i++)
#pragma unroll
            for (int e = 0; e < 4; e++) acc2[i][e] += a4[i] * b4[e];
    }
    float* kvp = g_kvpart + (((size_t)ct * Bsz + b) * Hn + h) * (Dh * Dh);
#pragma unroll
    for (int i = 0; i < 4; i++)
#pragma unroll
        for (int e = 0; e < 4; e++)
            kvp[(size_t)(ty*4 + i) * 64 + tx*4 + e] = acc2[i][e];
}

// ---------------------------------------------------------------------------
// Kernel 4: W2 (fp32, proven)
// ---------------------------------------------------------------------------
__global__ __launch_bounds__(256) void w2_kernel(const float* __restrict__ Wo) {
    const int ot = blockIdx.x;
    const int h  = blockIdx.y;
    const int b  = blockIdx.z;

    __shared__ float Wos[64][68];
    __shared__ float kvs[64][68];

    const int tid = threadIdx.x;
    const int tx = tid & 15, ty = tid >> 4;

#pragma unroll
    for (int q = 0; q < 4; q++) {
        const int idx = tid + q*256;
        const int r = idx >> 4, f4 = idx & 15;
        *(float4*)&Wos[r][f4*4] = *(const float4*)(Wo + (size_t)(ot*64 + r) * Cdim + h*64 + f4*4);
    }
#pragma unroll
    for (int q = 0; q < 4; q++) {
        const int idx = tid + q*256;
        const int d = idx >> 4, f4 = idx & 15;
        float4 s = make_float4(0.f, 0.f, 0.f, 0.f);
        for (int t = 0; t < 8; t++) {
            const float4 v = *(const float4*)(g_kvpart +
                (((size_t)t * Bsz + b) * Hn + h) * 4096 + (size_t)d * 64 + f4*4);
            s.x += v.x; s.y += v.y; s.z += v.z; s.w += v.w;
        }
        *(float4*)&kvs[d][f4*4] = s;
    }
    __syncthreads();

    float acc[4][4];
#pragma unroll
    for (int i = 0; i < 4; i++)
#pragma unroll
        for (int j = 0; j < 4; j++) acc[i][j] = 0.f;
    for (int e = 0; e < 64; e++) {
        float a4[4], b4[4];
#pragma unroll
        for (int i = 0; i < 4; i++) a4[i] = Wos[ty*4+i][e];
#pragma unroll
        for (int j = 0; j < 4; j++) b4[j] = kvs[tx*4+j][e];
#pragma unroll
        for (int i = 0; i < 4; i++)
#pragma unroll
            for (int j = 0; j < 4; j++) acc[i][j] += a4[i] * b4[j];
    }
    float* W2 = g_W2 + (size_t)b * Cdim * Cdim;
    const float inv = 1.f / 64.f;
#pragma unroll
    for (int i = 0; i < 4; i++)
#pragma unroll
        for (int j = 0; j < 4; j++)
            W2[(size_t)(ot*64 + ty*4 + i) * Cdim + h*64 + tx*4 + j] = acc[i][j] * inv;
}

// ---------------------------------------------------------------------------
// Kernel 5: W3 (fp32, proven): W3[b] = W2[b] @ Wq
// ---------------------------------------------------------------------------
__global__ __launch_bounds__(256) void w3_kernel(const float* __restrict__ Wq) {
    const int nt = blockIdx.x;
    const int mt = blockIdx.y;
    const int b  = blockIdx.z;
    const float* A = g_W2 + (size_t)b * Cdim * Cdim;

    __shared__ float As_[16][68];
    __shared__ float Bs_[16][68];

    const int tid = threadIdx.x;
    const int tx = tid & 15, ty = tid >> 4;

    float acc[4][4];
#pragma unroll
    for (int i = 0; i < 4; i++)
#pragma unroll
        for (int j = 0; j < 4; j++) acc[i][j] = 0.f;

    for (int k = 0; k < 512; k += 16) {
        const int row = tid >> 2, c4 = tid & 3;
        float4 a4 = *(const float4*)(A + (size_t)(mt*64 + row) * Cdim + k + c4*4);
        const int kr = tid >> 4, f4 = tid & 15;
        float4 b4 = *(const float4*)(Wq + (size_t)(k + kr) * Cdim + nt*64 + f4*4);
        __syncthreads();
        As_[c4*4+0][row] = a4.x; As_[c4*4+1][row] = a4.y;
        As_[c4*4+2][row] = a4.z; As_[c4*4+3][row] = a4.w;
        *(float4*)&Bs_[kr][f4*4] = b4;
        __syncthreads();
#pragma unroll
        for (int kk = 0; kk < 16; kk++) {
            float a[4], bb[4];
            *(float4*)&a[0]  = *(const float4*)&As_[kk][ty*4];
            *(float4*)&bb[0] = *(const float4*)&Bs_[kk][tx*4];
#pragma unroll
            for (int i = 0; i < 4; i++)
#pragma unroll
                for (int j = 0; j < 4; j++) acc[i][j] += a[i] * bb[j];
        }
    }
    float* W3 = g_W3 + (size_t)b * Cdim * Cdim;
#pragma unroll
    for (int i = 0; i < 4; i++)
#pragma unroll
        for (int j = 0; j < 4; j++)
            W3[(size_t)(mt*64 + ty*4 + i) * Cdim + nt*64 + tx*4 + j] = acc[i][j];
}

// ---------------------------------------------------------------------------
// Kernel 6: out; f32x2, 8m x 16n microtile (128 threads/block).
// out[b] = W3[b] @ Xl[b]  (M=512, N=8192, K=512)
// ---------------------------------------------------------------------------
__global__ __launch_bounds__(128, 2) void out_kernel(const float* __restrict__ Xl,
                                                     float* __restrict__ Out) {
    const int nt = blockIdx.x;
    const int mt = blockIdx.y;
    const int b  = blockIdx.z;
    const float* A  = g_W3 + (size_t)b * Cdim * Cdim;
    const float* Bm = Xl + (size_t)b * Cdim * Ldim;
    float* O        = Out + (size_t)b * Cdim * Ldim;

    __shared__ float As[16][132];   // [k][m]
    __shared__ float Bs[16][132];   // [k][n]

    const int tid = threadIdx.x;
    const int tx = tid & 7, ty = tid >> 3;
    const int n0 = nt * 128;

    // A loader: 128 rows x 4 float4-chunks (k-major rows of W3)
    int arow[4], ac4[4];
    // B loader: 16 k-rows x 32 float4-chunks (n-major rows of Xl)
    int bkr[4], bc32[4];
#pragma unroll
    for (int q = 0; q < 4; q++) {
        const int id = tid + q * 128;
        arow[q] = id >> 2;  ac4[q]  = id & 3;
        bkr[q]  = id >> 5;  bc32[q] = id & 31;
    }
    const float* pA[4];
    const float* pB[4];
#pragma unroll
    for (int q = 0; q < 4; q++) {
        pA[q] = A + (size_t)(mt*128 + arow[q]) * Cdim + ac4[q] * 4;
        pB[q] = Bm + (size_t)bkr[q] * Ldim + n0 + bc32[q] * 4;
    }

    unsigned long long acc[8][8];
#pragma unroll
    for (int i = 0; i < 8; i++)
#pragma unroll
        for (int j = 0; j < 8; j++) acc[i][j] = 0ull;

    float4 fa[4], fb[4];
#pragma unroll
    for (int q = 0; q < 4; q++) { fa[q] = *(const float4*)(pA[q]); fb[q] = *(const float4*)(pB[q]); }

    for (int k = 0; k < 512; k += 16) {
        __syncthreads();
#pragma unroll
        for (int q = 0; q < 4; q++) {
            As[ac4[q]*4+0][arow[q]] = fa[q].x; As[ac4[q]*4+1][arow[q]] = fa[q].y;
            As[ac4[q]*4+2][arow[q]] = fa[q].z; As[ac4[q]*4+3][arow[q]] = fa[q].w;
            *(float4*)&Bs[bkr[q]][bc32[q]*4] = fb[q];
        }
        __syncthreads();
        if (k + 16 < 512) {
#pragma unroll
            for (int q = 0; q < 4; q++) {
                fa[q] = *(const float4*)(pA[q] + k + 16);
                fb[q] = *(const float4*)(pB[q] + (size_t)(k + 16) * Ldim);
            }
        }
#pragma unroll
        for (int kk = 0; kk < 16; kk++) {
            float af[8];
            *(float4*)&af[0] = *(const float4*)&As[kk][ty*8];
            *(float4*)&af[4] = *(const float4*)&As[kk][ty*8 + 4];
            float4 bq0 = *(const float4*)&Bs[kk][tx*4];
            float4 bq1 = *(const float4*)&Bs[kk][32 + tx*4];
            float4 bq2 = *(const float4*)&Bs[kk][64 + tx*4];
            float4 bq3 = *(const float4*)&Bs[kk][96 + tx*4];
            unsigned long long bp[8];
            bp[0] = *(unsigned long long*)&bq0.x; bp[1] = *(unsigned long long*)&bq0.z;
            bp[2] = *(unsigned long long*)&bq1.x; bp[3] = *(unsigned long long*)&bq1.z;
            bp[4] = *(unsigned long long*)&bq2.x; bp[5] = *(unsigned long long*)&bq2.z;
            bp[6] = *(unsigned long long*)&bq3.x; bp[7] = *(unsigned long long*)&bq3.z;
#pragma unroll
            for (int i = 0; i < 8; i++) {
                const unsigned long long aa = dup2(af[i]);
#pragma unroll
                for (int j = 0; j < 8; j++) fma2(acc[i][j], aa, bp[j]);
            }
        }
    }

#pragma unroll
    for (int i = 0; i < 8; i++) {
        const int m = mt*128 + ty*8 + i;
#pragma unroll
        for (int c = 0; c < 4; c++) {
            const int n = n0 + 32 * c + tx * 4;
            float4 v = make_float4(lo32(acc[i][2*c]), hi32(acc[i][2*c]),
                                   lo32(acc[i][2*c+1]), hi32(acc[i][2*c+1]));
            *(float4*)(O + (size_t)m * Ldim + n) = v;
        }
    }
}

// ---------------------------------------------------------------------------
extern "C" void kernel_launch(void* const* d_in, const int* in_sizes, int n_in,
                              void* d_out, int out_size) {
    const float* x_local  = (const float*)d_in[0];
    const float* x_global = (const float*)d_in[1];
    const float* Wq       = (const float*)d_in[2];
    const float* Wk       = (const float*)d_in[3];
    const float* Wv       = (const float*)d_in[4];
    const float* Wo       = (const float*)d_in[5];
    float* out = (float*)d_out;

    gram_kernel<<<dim3(10, 4, 8), 128>>>(x_global);
    greduce_kernel<<<dim3(8192), 256>>>();
    kv_kernel<<<dim3(8, 8, 8), 256>>>(Wk, Wv);
    w2_kernel<<<dim3(8, 8, 8), 256>>>(Wo);
    w3_kernel<<<dim3(8, 8, 8), 256>>>(Wq);
    out_kernel<<<dim3(64, 4, 8), 128>>>(x_local, out);
}

// round 15
// speedup vs baseline: 1.9919x; 1.0822x over previous
#include <cuda_runtime.h>
#include <cstdint>

constexpr int Bsz  = 8;
constexpr int Cdim = 512;
constexpr int Ldim = 8192;
constexpr int Hn   = 8;
constexpr int Dh   = 64;
constexpr int KSPLIT = 8;   // gram split-K slabs

// ---------------- scratch (static device arrays; never passed as kernel args) --
__device__ float g_Gpart[(size_t)KSPLIT * Bsz * Cdim * Cdim];   // 64 MB
__device__ float g_G[(size_t)Bsz * Cdim * Cdim];
__device__ float g_kvpart[8ull * Bsz * Hn * Dh * Dh];
__device__ float g_W2[(size_t)Bsz * Cdim * Cdim];
__device__ float g_W3[(size_t)Bsz * Cdim * Cdim];

// packed dual-FMA helpers (base PTX, sm_100+)
static __device__ __forceinline__ unsigned long long dup2(float a) {
    unsigned long long r;
    asm("mov.b64 %0, {%1, %1};" : "=l"(r) : "f"(a));
    return r;
}
static __device__ __forceinline__ void fma2(unsigned long long& c,
                                            unsigned long long a,
                                            unsigned long long b) {
    asm("fma.rn.f32x2 %0, %1, %2, %0;" : "+l"(c) : "l"(a), "l"(b));
}
static __device__ __forceinline__ float lo32(unsigned long long v) {
    return __uint_as_float((unsigned)(v & 0xFFFFFFFFull));
}
static __device__ __forceinline__ float hi32(unsigned long long v) {
    return __uint_as_float((unsigned)(v >> 32));
}

// ---------------------------------------------------------------------------
// Kernel 1: Gram partials; f32x2 + register-prefetch (R11-proven inner loop).
// G[b] = Xg[b] @ Xg[b]^T, 10 symmetric 128x128 tile pairs, split-K=8 slabs
// (K=1024 per block) to kill the wave tail: 640 blocks vs 296 resident.
// ---------------------------------------------------------------------------
__global__ __launch_bounds__(256, 2) void gram_kernel(const float* __restrict__ Xg) {
    const int pair = blockIdx.x, ks = blockIdx.y, b = blockIdx.z;
    int ti = 0, t = pair;
    while (t >= 4 - ti) { t -= 4 - ti; ti++; }
    const int tj = ti + t;

    const float* X   = Xg + (size_t)b * Cdim * Ldim;
    const float* Ag0 = X + (size_t)ti * 128 * Ldim;
    const float* Bg0 = X + (size_t)tj * 128 * Ldim;
    const int k0 = ks * 1024;

    __shared__ float As[16][132];
    __shared__ float Bs[16][132];

    const int tid = threadIdx.x;
    const int tx = tid & 15, ty = tid >> 4;
    const int lrow = tid >> 2, lc4 = tid & 3;

    unsigned long long acc[8][4];
#pragma unroll
    for (int i = 0; i < 8; i++)
#pragma unroll
        for (int j = 0; j < 4; j++) acc[i][j] = 0ull;

    const float* ApA = Ag0 + (size_t)lrow * Ldim + lc4 * 4 + k0;
    const float* ApB = Ag0 + (size_t)(lrow + 64) * Ldim + lc4 * 4 + k0;
    const float* BpA = Bg0 + (size_t)lrow * Ldim + lc4 * 4 + k0;
    const float* BpB = Bg0 + (size_t)(lrow + 64) * Ldim + lc4 * 4 + k0;

    float4 a0 = *(const float4*)(ApA);
    float4 a1 = *(const float4*)(ApB);
    float4 b0 = *(const float4*)(BpA);
    float4 b1 = *(const float4*)(BpB);

    for (int kt = 0; kt < 1024; kt += 16) {
        __syncthreads();   // previous compute done before smem overwrite
        As[lc4*4+0][lrow]    = a0.x; As[lc4*4+1][lrow]    = a0.y;
        As[lc4*4+2][lrow]    = a0.z; As[lc4*4+3][lrow]    = a0.w;
        As[lc4*4+0][lrow+64] = a1.x; As[lc4*4+1][lrow+64] = a1.y;
        As[lc4*4+2][lrow+64] = a1.z; As[lc4*4+3][lrow+64] = a1.w;
        Bs[lc4*4+0][lrow]    = b0.x; Bs[lc4*4+1][lrow]    = b0.y;
        Bs[lc4*4+2][lrow]    = b0.z; Bs[lc4*4+3][lrow]    = b0.w;
        Bs[lc4*4+0][lrow+64] = b1.x; Bs[lc4*4+1][lrow+64] = b1.y;
        Bs[lc4*4+2][lrow+64] = b1.z; Bs[lc4*4+3][lrow+64] = b1.w;
        __syncthreads();
        if (kt + 16 < 1024) {   // prefetch next stage; LDG latency hides under compute
            a0 = *(const float4*)(ApA + kt + 16);
            a1 = *(const float4*)(ApB + kt + 16);
            b0 = *(const float4*)(BpA + kt + 16);
            b1 = *(const float4*)(BpB + kt + 16);
        }
#pragma unroll
        for (int kk = 0; kk < 16; kk++) {
            float af[8];
            *(float4*)&af[0] = *(const float4*)&As[kk][ty*4];
            *(float4*)&af[4] = *(const float4*)&As[kk][64 + ty*4];
            float4 bq0 = *(const float4*)&Bs[kk][tx*4];
            float4 bq1 = *(const float4*)&Bs[kk][64 + tx*4];
            unsigned long long bp[4];
            bp[0] = *(unsigned long long*)&bq0.x;
            bp[1] = *(unsigned long long*)&bq0.z;
            bp[2] = *(unsigned long long*)&bq1.x;
            bp[3] = *(unsigned long long*)&bq1.z;
#pragma unroll
            for (int i = 0; i < 8; i++) {
                const unsigned long long aa = dup2(af[i]);
#pragma unroll
                for (int j = 0; j < 4; j++) fma2(acc[i][j], aa, bp[j]);
            }
        }
    }

    float* Gp = g_Gpart + ((size_t)ks * Bsz + b) * Cdim * Cdim;
#pragma unroll
    for (int i = 0; i < 8; i++) {
        const int m = ti * 128 + ((i < 4) ? (ty*4 + i) : (64 + ty*4 + i - 4));
        float av[8];
#pragma unroll
        for (int j = 0; j < 4; j++) { av[2*j] = lo32(acc[i][j]); av[2*j+1] = hi32(acc[i][j]); }
#pragma unroll
        for (int j = 0; j < 8; j++) {
            const int n = tj * 128 + ((j < 4) ? (tx*4 + j) : (64 + tx*4 + j - 4));
            Gp[(size_t)m * Cdim + n] = av[j];
            if (ti != tj) Gp[(size_t)n * Cdim + m] = av[j];
        }
    }
}

// Kernel 2: reduce the 8 split-K slabs (deterministic).
__global__ void greduce_kernel() {
    const size_t n   = (size_t)Bsz * Cdim * Cdim;
    const size_t idx = (size_t)blockIdx.x * blockDim.x + threadIdx.x;
    if (idx < n) {
        float s = 0.f;
#pragma unroll
        for (int t = 0; t < KSPLIT; t++) s += g_Gpart[(size_t)t * n + idx];
        g_G[idx] = s;
    }
}

// ---------------------------------------------------------------------------
// Kernel 3: kv partials (fp32, proven): kv[b,h] = Wk_h @ G[b] @ Wv_h^T
// ---------------------------------------------------------------------------
__global__ __launch_bounds__(256) void kv_kernel(const float* __restrict__ Wk,
                                                 const float* __restrict__ Wv) {
    const int ct = blockIdx.x;
    const int h  = blockIdx.y;
    const int b  = blockIdx.z;
    const float* G = g_G + (size_t)b * Cdim * Cdim;
    const int c0 = ct * 64;

    __shared__ float Wks[16][68];
    __shared__ float Gs[16][68];
    __shared__ float Ts[64][68];
    __shared__ float Wvs[64][68];

    const int tid = threadIdx.x;
    const int tx = tid & 15, ty = tid >> 4;

    float acc[4][4];
#pragma unroll
    for (int i = 0; i < 4; i++)
#pragma unroll
        for (int j = 0; j < 4; j++) acc[i][j] = 0.f;

    for (int k = 0; k < 512; k += 16) {
        const int row = tid >> 2, c4 = tid & 3;
        float4 w4 = *(const float4*)(Wk + (size_t)(h*64 + row) * Cdim + k + c4*4);
        const int kr = tid >> 4, f4 = tid & 15;
        float4 g4 = *(const float4*)(G + (size_t)(k + kr) * Cdim + c0 + f4*4);
        __syncthreads();
        Wks[c4*4+0][row] = w4.x; Wks[c4*4+1][row] = w4.y;
        Wks[c4*4+2][row] = w4.z; Wks[c4*4+3][row] = w4.w;
        *(float4*)&Gs[kr][f4*4] = g4;
        __syncthreads();
#pragma unroll
        for (int kk = 0; kk < 16; kk++) {
            float a4[4], b4[4];
            *(float4*)&a4[0] = *(const float4*)&Wks[kk][ty*4];
            *(float4*)&b4[0] = *(const float4*)&Gs[kk][tx*4];
#pragma unroll
            for (int i = 0; i < 4; i++)
#pragma unroll
                for (int j = 0; j < 4; j++) acc[i][j] += a4[i] * b4[j];
        }
    }
#pragma unroll
    for (int i = 0; i < 4; i++)
#pragma unroll
        for (int j = 0; j < 4; j++) Ts[ty*4+i][tx*4+j] = acc[i][j];

#pragma unroll
    for (int q = 0; q < 4; q++) {
        const int idx = tid + q*256;
        const int er = idx >> 4, f4 = idx & 15;
        *(float4*)&Wvs[er][f4*4] = *(const float4*)(Wv + (size_t)(h*64 + er) * Cdim + c0 + f4*4);
    }
    __syncthreads();

    float acc2[4][4];
#pragma unroll
    for (int i = 0; i < 4; i++)
#pragma unroll
        for (int j = 0; j < 4; j++) acc2[i][j] = 0.f;
    for (int j = 0; j < 64; j++) {
        float a4[4], b4[4];
#pragma unroll
        for (int i = 0; i < 4; i++) a4[i] = Ts[ty*4+i][j];
#pragma unroll
        for (int e = 0; e < 4; e++) b4[e] = Wvs[tx*4+e][j];
#pragma unroll
        for (int i = 0; i < 4; i++)
#pragma unroll
            for (int e = 0; e < 4; e++) acc2[i][e] += a4[i] * b4[e];
    }
    float* kvp = g_kvpart + (((size_t)ct * Bsz + b) * Hn + h) * (Dh * Dh);
#pragma unroll
    for (int i = 0; i < 4; i++)
#pragma unroll
        for (int e = 0; e < 4; e++)
            kvp[(size_t)(ty*4 + i) * 64 + tx*4 + e] = acc2[i][e];
}

// ---------------------------------------------------------------------------
// Kernel 4: W2 (fp32, proven)
// ---------------------------------------------------------------------------
__global__ __launch_bounds__(256) void w2_kernel(const float* __restrict__ Wo) {
    const int ot = blockIdx.x;
    const int h  = blockIdx.y;
    const int b  = blockIdx.z;

    __shared__ float Wos[64][68];
    __shared__ float kvs[64][68];

    const int tid = threadIdx.x;
    const int tx = tid & 15, ty = tid >> 4;

#pragma unroll
    for (int q = 0; q < 4; q++) {
        const int idx = tid + q*256;
        const int r = idx >> 4, f4 = idx & 15;
        *(float4*)&Wos[r][f4*4] = *(const float4*)(Wo + (size_t)(ot*64 + r) * Cdim + h*64 + f4*4);
    }
#pragma unroll
    for (int q = 0; q < 4; q++) {
        const int idx = tid + q*256;
        const int d = idx >> 4, f4 = idx & 15;
        float4 s = make_float4(0.f, 0.f, 0.f, 0.f);
        for (int t = 0; t < 8; t++) {
            const float4 v = *(const float4*)(g_kvpart +
                (((size_t)t * Bsz + b) * Hn + h) * 4096 + (size_t)d * 64 + f4*4);
            s.x += v.x; s.y += v.y; s.z += v.z; s.w += v.w;
        }
        *(float4*)&kvs[d][f4*4] = s;
    }
    __syncthreads();

    float acc[4][4];
#pragma unroll
    for (int i = 0; i < 4; i++)
#pragma unroll
        for (int j = 0; j < 4; j++) acc[i][j] = 0.f;
    for (int e = 0; e < 64; e++) {
        float a4[4], b4[4];
#pragma unroll
        for (int i = 0; i < 4; i++) a4[i] = Wos[ty*4+i][e];
#pragma unroll
        for (int j = 0; j < 4; j++) b4[j] = kvs[tx*4+j][e];
#pragma unroll
        for (int i = 0; i < 4; i++)
#pragma unroll
            for (int j = 0; j < 4; j++) acc[i][j] += a4[i] * b4[j];
    }
    float* W2 = g_W2 + (size_t)b * Cdim * Cdim;
    const float inv = 1.f / 64.f;
#pragma unroll
    for (int i = 0; i < 4; i++)
#pragma unroll
        for (int j = 0; j < 4; j++)
            W2[(size_t)(ot*64 + ty*4 + i) * Cdim + h*64 + tx*4 + j] = acc[i][j] * inv;
}

// ---------------------------------------------------------------------------
// Kernel 5: W3 (fp32, proven): W3[b] = W2[b] @ Wq
// ---------------------------------------------------------------------------
__global__ __launch_bounds__(256) void w3_kernel(const float* __restrict__ Wq) {
    const int nt = blockIdx.x;
    const int mt = blockIdx.y;
    const int b  = blockIdx.z;
    const float* A = g_W2 + (size_t)b * Cdim * Cdim;

    __shared__ float As_[16][68];
    __shared__ float Bs_[16][68];

    const int tid = threadIdx.x;
    const int tx = tid & 15, ty = tid >> 4;

    float acc[4][4];
#pragma unroll
    for (int i = 0; i < 4; i++)
#pragma unroll
        for (int j = 0; j < 4; j++) acc[i][j] = 0.f;

    for (int k = 0; k < 512; k += 16) {
        const int row = tid >> 2, c4 = tid & 3;
        float4 a4 = *(const float4*)(A + (size_t)(mt*64 + row) * Cdim + k + c4*4);
        const int kr = tid >> 4, f4 = tid & 15;
        float4 b4 = *(const float4*)(Wq + (size_t)(k + kr) * Cdim + nt*64 + f4*4);
        __syncthreads();
        As_[c4*4+0][row] = a4.x; As_[c4*4+1][row] = a4.y;
        As_[c4*4+2][row] = a4.z; As_[c4*4+3][row] = a4.w;
        *(float4*)&Bs_[kr][f4*4] = b4;
        __syncthreads();
#pragma unroll
        for (int kk = 0; kk < 16; kk++) {
            float a[4], bb[4];
            *(float4*)&a[0]  = *(const float4*)&As_[kk][ty*4];
            *(float4*)&bb[0] = *(const float4*)&Bs_[kk][tx*4];
#pragma unroll
            for (int i = 0; i < 4; i++)
#pragma unroll
                for (int j = 0; j < 4; j++) acc[i][j] += a[i] * bb[j];
        }
    }
    float* W3 = g_W3 + (size_t)b * Cdim * Cdim;
#pragma unroll
    for (int i = 0; i < 4; i++)
#pragma unroll
        for (int j = 0; j < 4; j++)
            W3[(size_t)(mt*64 + ty*4 + i) * Cdim + nt*64 + tx*4 + j] = acc[i][j];
}

// ---------------------------------------------------------------------------
// Kernel 6: out; f32x2 + register-prefetch (R11-proven).
// out[b] = W3[b] @ Xl[b]  (M=512, N=8192, K=512)
// ---------------------------------------------------------------------------
__global__ __launch_bounds__(256, 2) void out_kernel(const float* __restrict__ Xl,
                                                     float* __restrict__ Out) {
    const int nt = blockIdx.x;
    const int mt = blockIdx.y;
    const int b  = blockIdx.z;
    const float* A  = g_W3 + (size_t)b * Cdim * Cdim;
    const float* Bm = Xl + (size_t)b * Cdim * Ldim;
    float* O        = Out + (size_t)b * Cdim * Ldim;

    __shared__ float As[16][132];
    __shared__ float Bs[16][132];

    const int tid = threadIdx.x;
    const int tx = tid & 15, ty = tid >> 4;
    const int arow = tid >> 2, ac4 = tid & 3;
    const int kr0 = tid >> 5, c40 = tid & 31;
    const int n0 = nt * 128;

    unsigned long long acc[8][4];
#pragma unroll
    for (int i = 0; i < 8; i++)
#pragma unroll
        for (int j = 0; j < 4; j++) acc[i][j] = 0ull;

    const float* ApA = A + (size_t)(mt*128 + arow) * Cdim + ac4 * 4;
    const float* ApB = A + (size_t)(mt*128 + arow + 64) * Cdim + ac4 * 4;
    const float* BpA = Bm + (size_t)kr0 * Ldim + n0 + c40 * 4;
    const float* BpB = Bm + (size_t)(kr0 + 8) * Ldim + n0 + c40 * 4;

    float4 a0 = *(const float4*)(ApA);
    float4 a1 = *(const float4*)(ApB);
    float4 b0 = *(const float4*)(BpA);
    float4 b1 = *(const float4*)(BpB);

    for (int k = 0; k < 512; k += 16) {
        __syncthreads();
        As[ac4*4+0][arow]    = a0.x; As[ac4*4+1][arow]    = a0.y;
        As[ac4*4+2][arow]    = a0.z; As[ac4*4+3][arow]    = a0.w;
        As[ac4*4+0][arow+64] = a1.x; As[ac4*4+1][arow+64] = a1.y;
        As[ac4*4+2][arow+64] = a1.z; As[ac4*4+3][arow+64] = a1.w;
        *(float4*)&Bs[kr0][c40*4]     = b0;
        *(float4*)&Bs[kr0 + 8][c40*4] = b1;
        __syncthreads();
        if (k + 16 < 512) {
            a0 = *(const float4*)(ApA + k + 16);
            a1 = *(const float4*)(ApB + k + 16);
            b0 = *(const float4*)(BpA + (size_t)(k + 16) * Ldim);
            b1 = *(const float4*)(BpB + (size_t)(k + 16) * Ldim);
        }
#pragma unroll
        for (int kk = 0; kk < 16; kk++) {
            float af[8];
            *(float4*)&af[0] = *(const float4*)&As[kk][ty*4];
            *(float4*)&af[4] = *(const float4*)&As[kk][64 + ty*4];
            float4 bq0 = *(const float4*)&Bs[kk][tx*4];
            float4 bq1 = *(const float4*)&Bs[kk][64 + tx*4];
            unsigned long long bp[4];
            bp[0] = *(unsigned long long*)&bq0.x;
            bp[1] = *(unsigned long long*)&bq0.z;
            bp[2] = *(unsigned long long*)&bq1.x;
            bp[3] = *(unsigned long long*)&bq1.z;
#pragma unroll
            for (int i = 0; i < 8; i++) {
                const unsigned long long aa = dup2(af[i]);
#pragma unroll
                for (int j = 0; j < 4; j++) fma2(acc[i][j], aa, bp[j]);
            }
        }
    }

#pragma unroll
    for (int i = 0; i < 8; i++) {
        const int m = mt*128 + ((i < 4) ? (ty*4 + i) : (64 + ty*4 + i - 4));
        float4 v0 = make_float4(lo32(acc[i][0]), hi32(acc[i][0]),
                                lo32(acc[i][1]), hi32(acc[i][1]));
        float4 v1 = make_float4(lo32(acc[i][2]), hi32(acc[i][2]),
                                lo32(acc[i][3]), hi32(acc[i][3]));
        *(float4*)(O + (size_t)m * Ldim + n0 + tx*4)      = v0;
        *(float4*)(O + (size_t)m * Ldim + n0 + 64 + tx*4) = v1;
    }
}

// ---------------------------------------------------------------------------
extern "C" void kernel_launch(void* const* d_in, const int* in_sizes, int n_in,
                              void* d_out, int out_size) {
    const float* x_local  = (const float*)d_in[0];
    const float* x_global = (const float*)d_in[1];
    const float* Wq       = (const float*)d_in[2];
    const float* Wk       = (const float*)d_in[3];
    const float* Wv       = (const float*)d_in[4];
    const float* Wo       = (const float*)d_in[5];
    float* out = (float*)d_out;

    gram_kernel<<<dim3(10, KSPLIT, 8), 256>>>(x_global);
    greduce_kernel<<<dim3(8192), 256>>>();
    kv_kernel<<<dim3(8, 8, 8), 256>>>(Wk, Wv);
    w2_kernel<<<dim3(8, 8, 8), 256>>>(Wo);
    w3_kernel<<<dim3(8, 8, 8), 256>>>(Wq);
    out_kernel<<<dim3(64, 4, 8), 256>>>(x_local, out);
}